// round 10
// baseline (speedup 1.0000x reference)
#include <cuda_runtime.h>
#include <cuda_bf16.h>
#include <math.h>
#include <stdint.h>

#define Bb 8
#define Tt 24
#define NN 263
#define Dd 512

// ---------------- scratch (static device globals; no allocation) ----------------
__device__ float g_P[71098368];      // 50496 x 1408  x-projections
__device__ float g_P0[2359296];      // 6144 x 384    agg0 projections
__device__ float g_P1[4718592];      // 12288 x 384   agg1 projections
__device__ float g_Wcat[720896];     // 1408 x 512
__device__ float g_Wcat0[196608];    // 384 x 512
__device__ float g_Wcat1[196608];    // 384 x 512
__device__ float g_sx0[786432];      // B*T*2*32*64
__device__ float g_sx1[1572864];     // B*T*2*64*64
__device__ float g_sg[6463488];      // 50496 x 128 (fp32)
__device__ float g_tgx[3231744];     // 8*263*12*128
__device__ float g_st[32317440];     // 50496 x 640 (fp32)
__device__ float g_lam;

// bf16 hi/lo planes (row counts padded to multiples of 128 where used as GEMM A)
__device__ __nv_bfloat16 g_xh[25886720],  g_xl[25886720];    // 50560 x 512
__device__ __nv_bfloat16 g_a0h[3145728],  g_a0l[3145728];    // 6144 x 512
__device__ __nv_bfloat16 g_a1h[6291456],  g_a1l[6291456];    // 12288 x 512
__device__ __nv_bfloat16 g_Wh[720896],    g_Wl[720896];      // 1408 x 512
__device__ __nv_bfloat16 g_W0h[196608],   g_W0l[196608];     // 384 x 512
__device__ __nv_bfloat16 g_W1h[196608],   g_W1l[196608];     // 384 x 512
__device__ __nv_bfloat16 g_sgh[6471680],  g_sgl[6471680];    // 50560 x 128
__device__ __nv_bfloat16 g_Wah[16384],    g_Wal[16384];      // 128 x 128
__device__ __nv_bfloat16 g_sth[32358400], g_stl[32358400];   // 50560 x 640
__device__ __nv_bfloat16 g_Woh[327680],   g_Wol[327680];     // 512 x 640

// ---------------- helpers ----------------
__device__ __forceinline__ float warpMax(float v){
    #pragma unroll
    for (int o=16;o;o>>=1) v = fmaxf(v, __shfl_xor_sync(0xffffffffu, v, o));
    return v;
}
__device__ __forceinline__ float warpSum(float v){
    #pragma unroll
    for (int o=16;o;o>>=1) v += __shfl_xor_sync(0xffffffffu, v, o);
    return v;
}
__device__ __forceinline__ uint32_t smem_u32(const void* p){
    return (uint32_t)__cvta_generic_to_shared(p);
}
__device__ __forceinline__ void cp16(uint32_t dst, const void* src){
    asm volatile("cp.async.cg.shared.global [%0], [%1], 16;" :: "r"(dst), "l"(src));
}

#define MMA_BF16(c, a, b) \
    asm volatile("mma.sync.aligned.m16n8k16.row.col.f32.bf16.bf16.f32 " \
        "{%0,%1,%2,%3},{%4,%5,%6,%7},{%8,%9},{%0,%1,%2,%3};" \
        : "+f"((c)[0]),"+f"((c)[1]),"+f"((c)[2]),"+f"((c)[3]) \
        : "r"((a)[0]),"r"((a)[1]),"r"((a)[2]),"r"((a)[3]),"r"((b)[0]),"r"((b)[1]))

#define LDSM4(r0,r1,r2,r3,addr) \
    asm volatile("ldmatrix.sync.aligned.m8n8.x4.shared.b16 {%0,%1,%2,%3}, [%4];" \
        : "=r"(r0),"=r"(r1),"=r"(r2),"=r"(r3) : "r"(addr))

// ---------------- split fp32 -> bf16 hi/lo planes ----------------
__global__ __launch_bounds__(256)
void split_bf16(const float* __restrict__ src, __nv_bfloat16* __restrict__ hi,
                __nv_bfloat16* __restrict__ lo, int n)
{
    int i = (blockIdx.x*256 + threadIdx.x)*4;
    if (i >= n) return;
    float4 v = *(const float4*)(src+i);
    __nv_bfloat16 h0=__float2bfloat16(v.x), h1=__float2bfloat16(v.y);
    __nv_bfloat16 h2=__float2bfloat16(v.z), h3=__float2bfloat16(v.w);
    __nv_bfloat16 l0=__float2bfloat16(v.x-__bfloat162float(h0));
    __nv_bfloat16 l1=__float2bfloat16(v.y-__bfloat162float(h1));
    __nv_bfloat16 l2=__float2bfloat16(v.z-__bfloat162float(h2));
    __nv_bfloat16 l3=__float2bfloat16(v.w-__bfloat162float(h3));
    uint32_t wh0 = ((uint32_t)__bfloat16_as_ushort(h1)<<16)|__bfloat16_as_ushort(h0);
    uint32_t wh1 = ((uint32_t)__bfloat16_as_ushort(h3)<<16)|__bfloat16_as_ushort(h2);
    uint32_t wl0 = ((uint32_t)__bfloat16_as_ushort(l1)<<16)|__bfloat16_as_ushort(l0);
    uint32_t wl1 = ((uint32_t)__bfloat16_as_ushort(l3)<<16)|__bfloat16_as_ushort(l2);
    *(uint2*)(hi+i) = make_uint2(wh0, wh1);
    *(uint2*)(lo+i) = make_uint2(wl0, wl1);
}

// ---------------- lam scalar ----------------
__global__ void lam_kernel(const float* __restrict__ lq1, const float* __restrict__ lk1,
                           const float* __restrict__ lq2, const float* __restrict__ lk2)
{
    int l = threadIdx.x;
    float a = lq1[l]*lk1[l];
    float b = lq2[l]*lk2[l];
    a = warpSum(a); b = warpSum(b);
    if (l == 0) g_lam = expf(a) - expf(b) + 0.2f;   // LAMBDA_INIT = 0.2
}

// ---------------- bf16 HMMA NT GEMM over 3 plane-pairs, 2-stage, BM=BN=128 ----------
// C[m, coff+n] = Ah*Bh + Al*Bh + Ah*Bl (+bias[n]); fp32 out.
// 256 threads = 8 warps in 2x4; warp tile 64x32. BK=64. smem rows stride 144B.
// A rows may be padded (zeros); stores guarded by Mreal.
__global__ __launch_bounds__(256, 2)
void gemm_tc(const __nv_bfloat16* __restrict__ Ah, const __nv_bfloat16* __restrict__ Al,
             const __nv_bfloat16* __restrict__ Bh, const __nv_bfloat16* __restrict__ Bl,
             float* __restrict__ C, const float* __restrict__ bias,
             int Mreal, int K, int ldc, int coff)
{
    extern __shared__ __align__(16) uint8_t smem[];
    const int ABUF = 128*144, STG = 2*ABUF;       // A 18KB + B 18KB per stage
    const int tid = threadIdx.x;
    const int bm = blockIdx.y*128, bn = blockIdx.x*128;
    const int warp = tid>>5, lane = tid&31;
    const int wm = warp & 1, wn = warp >> 1;       // wm: 64-row half, wn: 32-col quarter
    const int g = lane>>2, tg = lane&3;

    const int nkt  = K >> 6;
    const int ntot = 3*nkt;

    const int lrow = tid >> 1;                     // 0..127
    const int lch0 = (tid & 1) * 4;                // chunks lch0..lch0+3

    float acc[4][4][4];
    #pragma unroll
    for (int i=0;i<4;i++)
        #pragma unroll
        for (int j=0;j<4;j++)
            #pragma unroll
            for (int q=0;q<4;q++) acc[i][j][q] = 0.f;

    auto issue_tile = [&](int t, int buf){
        int pass = t / nkt;
        int k0   = (t - pass*nkt) << 6;
        const __nv_bfloat16* Ap = (pass==1) ? Al : Ah;
        const __nv_bfloat16* Bp = (pass==2) ? Bl : Bh;
        uint8_t* da = smem + buf*STG;
        uint8_t* db = da + ABUF;
        const __nv_bfloat16* ag = Ap + (size_t)(bm+lrow)*K + k0 + lch0*8;
        const __nv_bfloat16* bg = Bp + (size_t)(bn+lrow)*K + k0 + lch0*8;
        uint32_t sa = smem_u32(da + lrow*144 + lch0*16);
        uint32_t sb = smem_u32(db + lrow*144 + lch0*16);
        #pragma unroll
        for (int c=0;c<4;c++){
            cp16(sa + c*16, ag + c*8);
            cp16(sb + c*16, bg + c*8);
        }
        asm volatile("cp.async.commit_group;");
    };

    issue_tile(0, 0);
    issue_tile(1, 1);

    const int arow = wm*64 + (lane & 15);
    const int ach  = lane >> 4;
    const int brow = wn*32 + (lane & 7) + ((lane >> 4) << 3);
    const int bch  = (lane >> 3) & 1;

    for (int t = 0; t < ntot; t++){
        const int buf = t & 1;
        if (t + 1 < ntot) { asm volatile("cp.async.wait_group 1;"); }
        else              { asm volatile("cp.async.wait_group 0;"); }
        __syncthreads();
        const uint8_t* da = smem + buf*STG;
        const uint8_t* db = da + ABUF;
        #pragma unroll
        for (int kk = 0; kk < 4; kk++){
            uint32_t af[4][4];
            #pragma unroll
            for (int mi=0; mi<4; mi++){
                uint32_t ad = smem_u32(da + (arow + mi*16)*144 + (2*kk + ach)*16);
                LDSM4(af[mi][0], af[mi][1], af[mi][2], af[mi][3], ad);
            }
            uint32_t bf[4][2];
            #pragma unroll
            for (int ni2=0; ni2<2; ni2++){
                uint32_t bd = smem_u32(db + (brow + ni2*16)*144 + (2*kk + bch)*16);
                uint32_t r0,r1,r2,r3;
                LDSM4(r0,r1,r2,r3, bd);
                bf[2*ni2][0]=r0;   bf[2*ni2][1]=r1;
                bf[2*ni2+1][0]=r2; bf[2*ni2+1][1]=r3;
            }
            #pragma unroll
            for (int mi=0; mi<4; mi++)
                #pragma unroll
                for (int ni=0; ni<4; ni++)
                    MMA_BF16(acc[mi][ni], af[mi], bf[ni]);
        }
        __syncthreads();
        if (t + 2 < ntot) issue_tile(t+2, buf);
    }

    #pragma unroll
    for (int mi=0; mi<4; mi++){
        #pragma unroll
        for (int ni=0; ni<4; ni++){
            int gr = bm + wm*64 + mi*16 + g;
            int gc = bn + wn*32 + ni*8 + 2*tg;
            float b0 = bias ? bias[gc]   : 0.f;
            float b1 = bias ? bias[gc+1] : 0.f;
            float* Cp = C + (size_t)gr*ldc + coff + gc;
            if (gr < Mreal) {
                Cp[0] = acc[mi][ni][0] + b0;
                Cp[1] = acc[mi][ni][1] + b1;
            }
            if (gr + 8 < Mreal) {
                Cp += (size_t)8*ldc;
                Cp[0] = acc[mi][ni][2] + b0;
                Cp[1] = acc[mi][ni][3] + b1;
            }
        }
    }
}

// ---------------- spatial diff-attention (branch 1) -> st cols 0..255 ----------
__global__ __launch_bounds__(512)
void spatial_kernel(const float* __restrict__ P, float* __restrict__ st,
                    const float* __restrict__ ln_g, const float* __restrict__ ln_b)
{
    extern __shared__ float sm[];
    float* k1s = sm;                    // 263 x 36
    float* k2s = k1s + NN*36;           // 263 x 36
    float* vs  = k2s + NN*36;           // 263 x 64
    float* pc  = vs  + NN*64;           // 32 x 264
    float* qs  = pc  + 32*264;          // 16 x 64
    const int h = blockIdx.x, t = blockIdx.y, b = blockIdx.z;
    const size_t r0 = ((size_t)b*Tt + t) * NN;
    const int tid = threadIdx.x;

    for (int i = tid; i < NN*32; i += 512) {
        int m = i >> 5, d = i & 31;
        const float* row = P + (r0 + m) * 1408 + h*64;
        k1s[m*36+d] = row[256 + d];
        k2s[m*36+d] = row[288 + d];
    }
    for (int i = tid; i < NN*64; i += 512) {
        int m = i >> 6, e = i & 63;
        vs[i] = P[(r0+m)*1408 + 512 + h*64 + e];
    }
    __syncthreads();

    const float lam = g_lam;
    const int w = tid >> 5, l = tid & 31;
    float* qw  = qs + w*64;
    const float gl0 = ln_g[l], gl1 = ln_g[32+l];
    const float bl0 = ln_b[l], bl1 = ln_b[32+l];
    const float sc = 0.17677669529663687f;

    for (int nb = 2*w; nb < 272; nb += 32) {
        #pragma unroll
        for (int qi = 0; qi < 2; qi++) {
            int n = nb + qi;
            int nclamp = n < NN ? n : NN-1;
            const float* qrow = P + (r0+nclamp)*1408 + h*64;
            qw[l] = qrow[l]; qw[32+l] = qrow[32+l];
            __syncwarp();
            float sc1[9], sc2[9];
            #pragma unroll
            for (int mi=0; mi<9; mi++){ sc1[mi]=0.f; sc2[mi]=0.f; }
            #pragma unroll
            for (int dd=0; dd<8; dd++){
                float4 qa = *(const float4*)&qw[dd*4];
                float4 qb = *(const float4*)&qw[32+dd*4];
                #pragma unroll
                for (int mi=0; mi<9; mi++){
                    int m = l + (mi<<5);
                    int mc = m < NN ? m : 0;
                    float4 kA = *(const float4*)&k1s[mc*36 + dd*4];
                    float4 kB = *(const float4*)&k2s[mc*36 + dd*4];
                    sc1[mi] += qa.x*kA.x + qa.y*kA.y + qa.z*kA.z + qa.w*kA.w;
                    sc2[mi] += qb.x*kB.x + qb.y*kB.y + qb.z*kB.z + qb.w*kB.w;
                }
            }
            float mx1 = -1e30f, mx2 = -1e30f;
            #pragma unroll
            for (int mi=0; mi<9; mi++){
                int m = l + (mi<<5);
                if (m < NN){
                    sc1[mi] *= sc; sc2[mi] *= sc;
                    mx1 = fmaxf(mx1, sc1[mi]); mx2 = fmaxf(mx2, sc2[mi]);
                } else { sc1[mi] = -1e30f; sc2[mi] = -1e30f; }
            }
            mx1 = warpMax(mx1); mx2 = warpMax(mx2);
            float sum1 = 0.f, sum2 = 0.f;
            #pragma unroll
            for (int mi=0; mi<9; mi++){
                int m = l + (mi<<5);
                if (m < NN){
                    sc1[mi] = __expf(sc1[mi]-mx1);
                    sc2[mi] = __expf(sc2[mi]-mx2);
                    sum1 += sc1[mi]; sum2 += sc2[mi];
                }
            }
            sum1 = warpSum(sum1); sum2 = warpSum(sum2);
            float inv1 = 1.f/sum1, inv2 = lam/sum2;
            float* pcw = pc + (w*2+qi)*264;
            #pragma unroll
            for (int mi=0; mi<9; mi++){
                int m = l + (mi<<5);
                if (m < NN) pcw[m] = sc1[mi]*inv1 - sc2[mi]*inv2;
            }
            __syncwarp();
        }
        const float* p0 = pc + (w*2+0)*264;
        const float* p1 = pc + (w*2+1)*264;
        float a0a=0.f, a0b=0.f, a1a=0.f, a1b=0.f;
        #pragma unroll 4
        for (int m=0; m<NN; m++){
            float va = vs[m*64+l], vb = vs[m*64+32+l];
            float q0p = p0[m], q1p = p1[m];
            a0a += q0p*va; a0b += q0p*vb;
            a1a += q1p*va; a1b += q1p*vb;
        }
        #pragma unroll
        for (int qi = 0; qi < 2; qi++) {
            int n = nb + qi;
            if (n >= NN) continue;
            float x0 = qi ? a1a : a0a;
            float x1 = qi ? a1b : a0b;
            float mean = warpSum(x0 + x1) * (1.f/64.f);
            float d0 = x0 - mean, d1 = x1 - mean;
            float var = warpSum(d0*d0 + d1*d1) * (1.f/64.f);
            float rstd = rsqrtf(var + 1e-5f);
            float* orow = st + (r0+n)*640 + h*64;
            orow[l]    = (d0*rstd*gl0 + bl0)*0.8f;
            orow[32+l] = (d1*rstd*gl1 + bl1)*0.8f;
        }
        __syncwarp();
    }
}

// ---------------- agg branch attention (pre-mix) ----------------
__global__ __launch_bounds__(256)
void agg_attn(const float* __restrict__ Pa, float* __restrict__ sx, int Ni)
{
    __shared__ float ks[64*65], vsh[64*64], ps[8*64], qs2[8*64];
    const int h = blockIdx.x, t = blockIdx.y, b = blockIdx.z;
    const size_t r0 = ((size_t)b*Tt + t) * Ni;
    const int tid = threadIdx.x;
    for (int i = tid; i < Ni*64; i += 256) {
        int m = i >> 6, d = i & 63;
        const float* row = Pa + (r0+m)*384 + h*64;
        ks[m*65+d]  = row[128 + d];
        vsh[i] = row[256 + d];
    }
    __syncthreads();
    const int w = tid>>5, l = tid&31;
    float* pw = ps  + w*64;
    float* qw = qs2 + w*64;
    for (int n = w; n < Ni; n += 8) {
        const float* qrow = Pa + (r0+n)*384 + h*64;
        qw[l] = qrow[l]; qw[32+l] = qrow[32+l];
        __syncwarp();
        float scv[2];
        #pragma unroll
        for (int mi=0; mi<2; mi++){
            int m = l + (mi<<5);
            float s = -1e30f;
            if (m < Ni){
                const float* kr = ks + m*65;
                float ts = 0.f;
                #pragma unroll
                for (int d=0; d<64; d++) ts += qw[d]*kr[d];
                s = ts * 0.125f;
            }
            scv[mi] = s;
        }
        float mx = warpMax(fmaxf(scv[0], scv[1]));
        float sum = 0.f;
        #pragma unroll
        for (int mi=0; mi<2; mi++){
            int m = l + (mi<<5);
            if (m < Ni){ float e = __expf(scv[mi]-mx); pw[m] = e; sum += e; }
        }
        sum = warpSum(sum);
        __syncwarp();
        float aa = 0.f, ab = 0.f;
        for (int m=0; m<Ni; m++){
            float e = pw[m];
            aa += e*vsh[m*64+l];
            ab += e*vsh[m*64+32+l];
        }
        float inv = 1.f/sum;
        float* o = sx + ((((size_t)b*Tt+t)*2 + h)*Ni + n)*64;
        o[l] = aa*inv; o[32+l] = ab*inv;
        __syncwarp();
    }
}

// ---------------- mix agg branches through M0/M1 ----------------
__global__ __launch_bounds__(128)
void combine_sg(const float* __restrict__ sx0, const float* __restrict__ sx1,
                const float* __restrict__ M0, const float* __restrict__ M1,
                float* __restrict__ sg)
{
    const int n = blockIdx.x, t = blockIdx.y, b = blockIdx.z;
    const int j = threadIdx.x, h = j>>6, d = j&63;
    const size_t bt = (size_t)b*Tt + t;
    float acc = 0.f;
    const float* s0 = sx0 + (bt*2+h)*(32*64) + d;
    #pragma unroll 4
    for (int m=0; m<32; m++) acc += M0[m*NN+n] * s0[m*64];
    const float* s1 = sx1 + (bt*2+h)*(64*64) + d;
    #pragma unroll 4
    for (int m=0; m<64; m++) acc += M1[m*NN+n] * s1[m*64];
    sg[(bt*NN+n)*128 + j] = acc;
}

// ---------------- temporal attention (t_x + tgx fused) ----------------
__global__ __launch_bounds__(128)
void temporal_kernel(const float* __restrict__ P, const float* __restrict__ q_agg,
                     float* __restrict__ st, float* __restrict__ tgx)
{
    extern __shared__ float sm[];
    const int n = blockIdx.x, b = blockIdx.y;
    const int wid = threadIdx.x >> 5, l = threadIdx.x & 31;
    const int w = wid & 1;
    const int half = wid >> 1;
    float* base = sm + w*6240;
    float* kts = base;
    float* vts = base + 1560;
    float* kgs = base + 3096;
    float* vgs = base + 4656;
    float* qp  = sm + 2*6240 + wid*96;
    float* qsh = qp;
    float* psh = qp + 64;
    for (int i = half*768 + l; i < half*768 + 768; i += 32){
        int t = i>>6, d = i&63;
        const float* row = P + (((size_t)b*Tt+t)*NN + n)*1408 + w*64;
        kts[t*65+d] = row[896+d];
        vts[t*64+d] = row[1024+d];
        kgs[t*65+d] = row[1152+d];
        vgs[t*64+d] = row[1280+d];
    }
    __syncthreads();
    for (int tq = half*12; tq < half*12 + 12; tq++){
        const float* qrow = P + (((size_t)b*Tt+tq)*NN + n)*1408 + w*64 + 768;
        qsh[l] = qrow[l]; qsh[32+l] = qrow[32+l];
        __syncwarp();
        float s = -1e30f;
        if (l < Tt){
            const float* kr = kts + l*65;
            float ts = 0.f;
            #pragma unroll
            for (int d=0; d<64; d++) ts += qsh[d]*kr[d];
            s = ts*0.125f;
        }
        float mx = warpMax(s);
        float e = (l < Tt) ? __expf(s-mx) : 0.f;
        float sum = warpSum(e);
        psh[l] = e;
        __syncwarp();
        float aa = 0.f, ab = 0.f;
        #pragma unroll
        for (int ss=0; ss<Tt; ss++){
            float p = psh[ss];
            aa += p*vts[ss*64+l]; ab += p*vts[ss*64+32+l];
        }
        float inv = 1.f/sum;
        float* o = st + (((size_t)b*Tt+tq)*NN + n)*640 + 384 + w*64;
        o[l] = aa*inv; o[32+l] = ab*inv;
        __syncwarp();
    }
    for (int sg_ = half*6; sg_ < half*6 + 6; sg_++){
        const float* qrow = q_agg + ((size_t)n*12 + sg_)*128 + w*64;
        qsh[l] = qrow[l]; qsh[32+l] = qrow[32+l];
        __syncwarp();
        float s = -1e30f;
        if (l < Tt){
            const float* kr = kgs + l*65;
            float ts = 0.f;
            #pragma unroll
            for (int d=0; d<64; d++) ts += qsh[d]*kr[d];
            s = ts*0.125f;
        }
        float mx = warpMax(s);
        float e = (l < Tt) ? __expf(s-mx) : 0.f;
        float sum = warpSum(e);
        psh[l] = e;
        __syncwarp();
        float aa = 0.f, ab = 0.f;
        #pragma unroll
        for (int ss=0; ss<Tt; ss++){
            float p = psh[ss];
            aa += p*vgs[ss*64+l]; ab += p*vgs[ss*64+32+l];
        }
        float inv = 1.f/sum;
        float* o = tgx + (((size_t)b*NN+n)*12 + sg_)*128 + w*64;
        o[l] = aa*inv; o[32+l] = ab*inv;
        __syncwarp();
    }
}

// ---------------- tg: mix tgx through tmp_map -> st cols 512..639 ------------
__global__ __launch_bounds__(128)
void tg_scatter(const float* __restrict__ tmp_map, const float* __restrict__ tgx,
                float* __restrict__ st)
{
    const int n = blockIdx.x, t = blockIdx.y, b = blockIdx.z;
    const int j = threadIdx.x;
    const float* tm = tmp_map + (((size_t)b*NN + n)*Tt + t)*12;
    const float* g  = tgx + ((size_t)b*NN + n)*12*128 + j;
    float acc = 0.f;
    #pragma unroll
    for (int ss=0; ss<12; ss++) acc += tm[ss]*g[ss*128];
    st[(((size_t)b*Tt+t)*NN + n)*640 + 512 + j] = acc;
}

// ---------------- host ----------------
static inline void split_launch(const float* src, __nv_bfloat16* hi, __nv_bfloat16* lo,
                                int n, cudaStream_t s){
    split_bf16<<<(n/4 + 255)/256, 256, 0, s>>>(src, hi, lo, n);
}

extern "C" void kernel_launch(void* const* d_in, const int* in_sizes, int n_in,
                              void* d_out, int out_size)
{
    (void)in_sizes; (void)n_in; (void)out_size;
    const float* x       = (const float*)d_in[0];
    const float* agg_x0  = (const float*)d_in[1];
    const float* agg_x1  = (const float*)d_in[2];
    const float* tmp_map = (const float*)d_in[3];

    float *P, *P0, *P1, *Wcat, *Wcat0, *Wcat1, *sx0, *sx1, *sg, *tgx, *st;
    cudaGetSymbolAddress((void**)&P,     g_P);
    cudaGetSymbolAddress((void**)&P0,    g_P0);
    cudaGetSymbolAddress((void**)&P1,    g_P1);
    cudaGetSymbolAddress((void**)&Wcat,  g_Wcat);
    cudaGetSymbolAddress((void**)&Wcat0, g_Wcat0);
    cudaGetSymbolAddress((void**)&Wcat1, g_Wcat1);
    cudaGetSymbolAddress((void**)&sx0,   g_sx0);
    cudaGetSymbolAddress((void**)&sx1,   g_sx1);
    cudaGetSymbolAddress((void**)&sg,    g_sg);
    cudaGetSymbolAddress((void**)&tgx,   g_tgx);
    cudaGetSymbolAddress((void**)&st,    g_st);

    __nv_bfloat16 *xh,*xl,*a0h,*a0l,*a1h,*a1l,*Wh,*Wl,*W0h,*W0l,*W1h,*W1l;
    __nv_bfloat16 *sgh,*sgl,*Wah,*Wal,*sth,*stl,*Woh,*Wol;
    cudaGetSymbolAddress((void**)&xh,  g_xh);  cudaGetSymbolAddress((void**)&xl,  g_xl);
    cudaGetSymbolAddress((void**)&a0h, g_a0h); cudaGetSymbolAddress((void**)&a0l, g_a0l);
    cudaGetSymbolAddress((void**)&a1h, g_a1h); cudaGetSymbolAddress((void**)&a1l, g_a1l);
    cudaGetSymbolAddress((void**)&Wh,  g_Wh);  cudaGetSymbolAddress((void**)&Wl,  g_Wl);
    cudaGetSymbolAddress((void**)&W0h, g_W0h); cudaGetSymbolAddress((void**)&W0l, g_W0l);
    cudaGetSymbolAddress((void**)&W1h, g_W1h); cudaGetSymbolAddress((void**)&W1l, g_W1l);
    cudaGetSymbolAddress((void**)&sgh, g_sgh); cudaGetSymbolAddress((void**)&sgl, g_sgl);
    cudaGetSymbolAddress((void**)&Wah, g_Wah); cudaGetSymbolAddress((void**)&Wal, g_Wal);
    cudaGetSymbolAddress((void**)&sth, g_sth); cudaGetSymbolAddress((void**)&stl, g_stl);
    cudaGetSymbolAddress((void**)&Woh, g_Woh); cudaGetSymbolAddress((void**)&Wol, g_Wol);

    cudaFuncSetAttribute(gemm_tc,         cudaFuncAttributeMaxDynamicSharedMemorySize, 73728);
    cudaFuncSetAttribute(spatial_kernel,  cudaFuncAttributeMaxDynamicSharedMemorySize, 180960);
    cudaFuncSetAttribute(temporal_kernel, cudaFuncAttributeMaxDynamicSharedMemorySize, 51456);

    cudaStream_t s = 0;
    const size_t W512 = (size_t)512 * sizeof(float);
    cudaMemcpyAsync(Wcat + (size_t)   0*512, d_in[4],  256*W512, cudaMemcpyDeviceToDevice, s);
    cudaMemcpyAsync(Wcat + (size_t) 256*512, d_in[5],  256*W512, cudaMemcpyDeviceToDevice, s);
    cudaMemcpyAsync(Wcat + (size_t) 512*512, d_in[6],  256*W512, cudaMemcpyDeviceToDevice, s);
    cudaMemcpyAsync(Wcat + (size_t) 768*512, d_in[23], 128*W512, cudaMemcpyDeviceToDevice, s);
    cudaMemcpyAsync(Wcat + (size_t) 896*512, d_in[24], 128*W512, cudaMemcpyDeviceToDevice, s);
    cudaMemcpyAsync(Wcat + (size_t)1024*512, d_in[25], 128*W512, cudaMemcpyDeviceToDevice, s);
    cudaMemcpyAsync(Wcat + (size_t)1152*512, d_in[27], 128*W512, cudaMemcpyDeviceToDevice, s);
    cudaMemcpyAsync(Wcat + (size_t)1280*512, d_in[28], 128*W512, cudaMemcpyDeviceToDevice, s);
    cudaMemcpyAsync(Wcat0 + (size_t)  0*512, d_in[13], 128*W512, cudaMemcpyDeviceToDevice, s);
    cudaMemcpyAsync(Wcat0 + (size_t)128*512, d_in[14], 128*W512, cudaMemcpyDeviceToDevice, s);
    cudaMemcpyAsync(Wcat0 + (size_t)256*512, d_in[15], 128*W512, cudaMemcpyDeviceToDevice, s);
    cudaMemcpyAsync(Wcat1 + (size_t)  0*512, d_in[16], 128*W512, cudaMemcpyDeviceToDevice, s);
    cudaMemcpyAsync(Wcat1 + (size_t)128*512, d_in[17], 128*W512, cudaMemcpyDeviceToDevice, s);
    cudaMemcpyAsync(Wcat1 + (size_t)256*512, d_in[18], 128*W512, cudaMemcpyDeviceToDevice, s);

    lam_kernel<<<1,32,0,s>>>((const float*)d_in[7], (const float*)d_in[8],
                             (const float*)d_in[9], (const float*)d_in[10]);

    // splits for projection inputs/weights
    split_launch(x,       xh,  xl,  50496*512, s);
    split_launch(agg_x0,  a0h, a0l, 6144*512, s);
    split_launch(agg_x1,  a1h, a1l, 12288*512, s);
    split_launch(Wcat,    Wh,  Wl,  1408*512, s);
    split_launch(Wcat0,   W0h, W0l, 384*512, s);
    split_launch(Wcat1,   W1h, W1l, 384*512, s);
    split_launch((const float*)d_in[21], Wah, Wal, 128*128, s);
    split_launch((const float*)d_in[29], Woh, Wol, 512*640, s);

    // projections (HMMA bf16 3-pass, 128x128 tiles)
    gemm_tc<<<dim3(11, 395), 256, 73728, s>>>(xh, xl, Wh, Wl, P, nullptr,
                                              50496, 512, 1408, 0);
    gemm_tc<<<dim3(3,   48), 256, 73728, s>>>(a0h, a0l, W0h, W0l, P0, nullptr,
                                              6144, 512, 384, 0);
    gemm_tc<<<dim3(3,   96), 256, 73728, s>>>(a1h, a1l, W1h, W1l, P1, nullptr,
                                              12288, 512, 384, 0);

    // branch 1: spatial diff attention -> st[:,0:256]
    spatial_kernel<<<dim3(4, Tt, Bb), 512, 180960, s>>>(P, st,
        (const float*)d_in[11], (const float*)d_in[12]);

    // branch 2: agg attention + mix + Wagg -> st[:,256:384]
    agg_attn<<<dim3(2, Tt, Bb), 256, 0, s>>>(P0, sx0, 32);
    agg_attn<<<dim3(2, Tt, Bb), 256, 0, s>>>(P1, sx1, 64);
    combine_sg<<<dim3(NN, Tt, Bb), 128, 0, s>>>(sx0, sx1,
        (const float*)d_in[19], (const float*)d_in[20], sg);
    split_launch(sg, sgh, sgl, 50496*128, s);
    gemm_tc<<<dim3(1, 395), 256, 73728, s>>>(sgh, sgl, Wah, Wal, st,
        (const float*)d_in[22], 50496, 128, 640, 256);

    // branches 3+4: temporal attention -> st[:,384:512]; tg -> st[:,512:640]
    temporal_kernel<<<dim3(NN, Bb), 128, 51456, s>>>(P, (const float*)d_in[26], st, tgx);
    tg_scatter<<<dim3(NN, Tt, Bb), 128, 0, s>>>(tmp_map, tgx, st);

    // output projection
    split_launch(st, sth, stl, 50496*640, s);
    gemm_tc<<<dim3(4, 395), 256, 73728, s>>>(sth, stl, Woh, Wol, (float*)d_out,
        (const float*)d_in[30], 50496, 640, 512, 0);
}

// round 11
// speedup vs baseline: 1.2227x; 1.2227x over previous
#include <cuda_runtime.h>
#include <cuda_bf16.h>
#include <math.h>
#include <stdint.h>

#define Bb 8
#define Tt 24
#define NN 263
#define Dd 512

// ---------------- scratch (static device globals; no allocation) ----------------
__device__ float g_P[71098368];      // 50496 x 1408  x-projections
__device__ float g_P0[2359296];      // 6144 x 384    agg0 projections
__device__ float g_P1[4718592];      // 12288 x 384   agg1 projections
__device__ float g_Wcat[720896];     // 1408 x 512
__device__ float g_Wcat0[196608];    // 384 x 512
__device__ float g_Wcat1[196608];    // 384 x 512
__device__ float g_sx0[786432];      // B*T*2*32*64
__device__ float g_sx1[1572864];     // B*T*2*64*64
__device__ float g_sg[6463488];      // 50496 x 128 (fp32)
__device__ float g_tgx[3231744];     // 8*263*12*128
__device__ float g_st[32317440];     // 50496 x 640 (fp32)
__device__ float g_lam;

// bf16 hi/lo planes
__device__ __nv_bfloat16 g_xh[25853952],  g_xl[25853952];    // 50496 x 512
__device__ __nv_bfloat16 g_a0h[3145728],  g_a0l[3145728];    // 6144 x 512
__device__ __nv_bfloat16 g_a1h[6291456],  g_a1l[6291456];    // 12288 x 512
__device__ __nv_bfloat16 g_Wh[720896],    g_Wl[720896];      // 1408 x 512
__device__ __nv_bfloat16 g_W0h[196608],   g_W0l[196608];     // 384 x 512
__device__ __nv_bfloat16 g_W1h[196608],   g_W1l[196608];     // 384 x 512
__device__ __nv_bfloat16 g_sgh[6463488],  g_sgl[6463488];    // 50496 x 128
__device__ __nv_bfloat16 g_Wah[16384],    g_Wal[16384];      // 128 x 128
__device__ __nv_bfloat16 g_sth[32317440], g_stl[32317440];   // 50496 x 640
__device__ __nv_bfloat16 g_Woh[327680],   g_Wol[327680];     // 512 x 640

// ---------------- helpers ----------------
__device__ __forceinline__ float warpMax(float v){
    #pragma unroll
    for (int o=16;o;o>>=1) v = fmaxf(v, __shfl_xor_sync(0xffffffffu, v, o));
    return v;
}
__device__ __forceinline__ float warpSum(float v){
    #pragma unroll
    for (int o=16;o;o>>=1) v += __shfl_xor_sync(0xffffffffu, v, o);
    return v;
}
__device__ __forceinline__ uint32_t smem_u32(const void* p){
    return (uint32_t)__cvta_generic_to_shared(p);
}
__device__ __forceinline__ void cp16(uint32_t dst, const void* src){
    asm volatile("cp.async.cg.shared.global [%0], [%1], 16;" :: "r"(dst), "l"(src));
}

#define MMA_BF16(c, a, b) \
    asm volatile("mma.sync.aligned.m16n8k16.row.col.f32.bf16.bf16.f32 " \
        "{%0,%1,%2,%3},{%4,%5,%6,%7},{%8,%9},{%0,%1,%2,%3};" \
        : "+f"((c)[0]),"+f"((c)[1]),"+f"((c)[2]),"+f"((c)[3]) \
        : "r"((a)[0]),"r"((a)[1]),"r"((a)[2]),"r"((a)[3]),"r"((b)[0]),"r"((b)[1]))

#define LDSM4(r0,r1,r2,r3,addr) \
    asm volatile("ldmatrix.sync.aligned.m8n8.x4.shared.b16 {%0,%1,%2,%3}, [%4];" \
        : "=r"(r0),"=r"(r1),"=r"(r2),"=r"(r3) : "r"(addr))

// ---------------- split fp32 -> bf16 hi/lo planes ----------------
__global__ __launch_bounds__(256)
void split_bf16(const float* __restrict__ src, __nv_bfloat16* __restrict__ hi,
                __nv_bfloat16* __restrict__ lo, int n)
{
    int i = (blockIdx.x*256 + threadIdx.x)*4;
    if (i >= n) return;
    float4 v = *(const float4*)(src+i);
    __nv_bfloat16 h0=__float2bfloat16(v.x), h1=__float2bfloat16(v.y);
    __nv_bfloat16 h2=__float2bfloat16(v.z), h3=__float2bfloat16(v.w);
    __nv_bfloat16 l0=__float2bfloat16(v.x-__bfloat162float(h0));
    __nv_bfloat16 l1=__float2bfloat16(v.y-__bfloat162float(h1));
    __nv_bfloat16 l2=__float2bfloat16(v.z-__bfloat162float(h2));
    __nv_bfloat16 l3=__float2bfloat16(v.w-__bfloat162float(h3));
    uint32_t wh0 = ((uint32_t)__bfloat16_as_ushort(h1)<<16)|__bfloat16_as_ushort(h0);
    uint32_t wh1 = ((uint32_t)__bfloat16_as_ushort(h3)<<16)|__bfloat16_as_ushort(h2);
    uint32_t wl0 = ((uint32_t)__bfloat16_as_ushort(l1)<<16)|__bfloat16_as_ushort(l0);
    uint32_t wl1 = ((uint32_t)__bfloat16_as_ushort(l3)<<16)|__bfloat16_as_ushort(l2);
    *(uint2*)(hi+i) = make_uint2(wh0, wh1);
    *(uint2*)(lo+i) = make_uint2(wl0, wl1);
}

// ---------------- lam scalar ----------------
__global__ void lam_kernel(const float* __restrict__ lq1, const float* __restrict__ lk1,
                           const float* __restrict__ lq2, const float* __restrict__ lk2)
{
    int l = threadIdx.x;
    float a = lq1[l]*lk1[l];
    float b = lq2[l]*lk2[l];
    a = warpSum(a); b = warpSum(b);
    if (l == 0) g_lam = expf(a) - expf(b) + 0.2f;   // LAMBDA_INIT = 0.2
}

// ---------------- bf16 HMMA NT GEMM, 4-plane tiles, single K sweep ----------------
// C[m, coff+n] = Ah*Bh + Al*Bh + Ah*Bl (+bias[n]); fp32 out.
// BM=64, BN=128, BK=64. Per K-tile: load Ah/Al/Bh/Bl planes once, do all 3 MMA sets.
// 256 threads = 8 warps (2m x 4n), warp tile 32x32. smem rows stride 144B.
// Stage = (64+64+128+128)*144 = 55296 B; 2 stages = 110592 B -> 2 CTAs/SM (221KB).
__global__ __launch_bounds__(256, 2)
void gemm_tc(const __nv_bfloat16* __restrict__ Ah, const __nv_bfloat16* __restrict__ Al,
             const __nv_bfloat16* __restrict__ Bh, const __nv_bfloat16* __restrict__ Bl,
             float* __restrict__ C, const float* __restrict__ bias,
             int K, int ldc, int coff)
{
    extern __shared__ __align__(16) uint8_t smem[];
    const int AH_OFF = 0, AL_OFF = 64*144, BH_OFF = 128*144, BL_OFF = 256*144;
    const int STG = 384*144;
    const int tid = threadIdx.x;
    const int bm = blockIdx.y*64, bn = blockIdx.x*128;
    const int warp = tid>>5, lane = tid&31;
    const int wm = warp & 1, wn = warp >> 1;
    const int g = lane>>2, tg = lane&3;

    const int nkt = K >> 6;

    float acc[2][4][4];
    #pragma unroll
    for (int i=0;i<2;i++)
        #pragma unroll
        for (int j=0;j<4;j++)
            #pragma unroll
            for (int q=0;q<4;q++) acc[i][j][q] = 0.f;

    auto issue_tile = [&](int kt, int buf){
        const int k0 = kt << 6;
        uint8_t* stg = smem + buf*STG;
        #pragma unroll
        for (int i = 0; i < 12; i++){
            int idx = tid + i*256;          // 0..3071
            int row = idx >> 3, ch = idx & 7;
            const __nv_bfloat16* src;
            if      (row < 64)  src = Ah + (size_t)(bm + row      )*K + k0 + ch*8;
            else if (row < 128) src = Al + (size_t)(bm + row - 64 )*K + k0 + ch*8;
            else if (row < 256) src = Bh + (size_t)(bn + row - 128)*K + k0 + ch*8;
            else                src = Bl + (size_t)(bn + row - 256)*K + k0 + ch*8;
            cp16(smem_u32(stg + row*144 + ch*16), src);
        }
        asm volatile("cp.async.commit_group;");
    };

    issue_tile(0, 0);
    if (nkt > 1) issue_tile(1, 1);

    const int arow = wm*32 + (lane & 15);
    const int ach  = lane >> 4;
    const int brow = wn*32 + (lane & 7) + ((lane >> 4) << 3);
    const int bch  = (lane >> 3) & 1;

    for (int t = 0; t < nkt; t++){
        const int buf = t & 1;
        if (t + 1 < nkt) { asm volatile("cp.async.wait_group 1;"); }
        else             { asm volatile("cp.async.wait_group 0;"); }
        __syncthreads();
        const uint8_t* stg = smem + buf*STG;
        #pragma unroll
        for (int kk = 0; kk < 4; kk++){
            uint32_t afh[2][4], afl[2][4];
            #pragma unroll
            for (int mi=0; mi<2; mi++){
                int ro = (arow + mi*16)*144 + (2*kk + ach)*16;
                LDSM4(afh[mi][0], afh[mi][1], afh[mi][2], afh[mi][3],
                      smem_u32(stg + AH_OFF + ro));
                LDSM4(afl[mi][0], afl[mi][1], afl[mi][2], afl[mi][3],
                      smem_u32(stg + AL_OFF + ro));
            }
            uint32_t bfh[4][2], bfl[4][2];
            #pragma unroll
            for (int ni2=0; ni2<2; ni2++){
                int ro = (brow + ni2*16)*144 + (2*kk + bch)*16;
                uint32_t r0,r1,r2,r3;
                LDSM4(r0,r1,r2,r3, smem_u32(stg + BH_OFF + ro));
                bfh[2*ni2][0]=r0;   bfh[2*ni2][1]=r1;
                bfh[2*ni2+1][0]=r2; bfh[2*ni2+1][1]=r3;
                LDSM4(r0,r1,r2,r3, smem_u32(stg + BL_OFF + ro));
                bfl[2*ni2][0]=r0;   bfl[2*ni2][1]=r1;
                bfl[2*ni2+1][0]=r2; bfl[2*ni2+1][1]=r3;
            }
            #pragma unroll
            for (int mi=0; mi<2; mi++)
                #pragma unroll
                for (int ni=0; ni<4; ni++){
                    MMA_BF16(acc[mi][ni], afh[mi], bfh[ni]);
                    MMA_BF16(acc[mi][ni], afl[mi], bfh[ni]);
                    MMA_BF16(acc[mi][ni], afh[mi], bfl[ni]);
                }
        }
        __syncthreads();
        if (t + 2 < nkt) issue_tile(t+2, buf);
    }

    #pragma unroll
    for (int mi=0; mi<2; mi++){
        #pragma unroll
        for (int ni=0; ni<4; ni++){
            int gr = bm + wm*32 + mi*16 + g;
            int gc = bn + wn*32 + ni*8 + 2*tg;
            float b0 = bias ? bias[gc]   : 0.f;
            float b1 = bias ? bias[gc+1] : 0.f;
            float* Cp = C + (size_t)gr*ldc + coff + gc;
            Cp[0] = acc[mi][ni][0] + b0;
            Cp[1] = acc[mi][ni][1] + b1;
            Cp += (size_t)8*ldc;
            Cp[0] = acc[mi][ni][2] + b0;
            Cp[1] = acc[mi][ni][3] + b1;
        }
    }
}

// ---------------- spatial diff-attention (branch 1) -> st cols 0..255 ----------
__global__ __launch_bounds__(512)
void spatial_kernel(const float* __restrict__ P, float* __restrict__ st,
                    const float* __restrict__ ln_g, const float* __restrict__ ln_b)
{
    extern __shared__ float sm[];
    float* k1s = sm;                    // 263 x 36
    float* k2s = k1s + NN*36;           // 263 x 36
    float* vs  = k2s + NN*36;           // 263 x 64
    float* pc  = vs  + NN*64;           // 32 x 264
    float* qs  = pc  + 32*264;          // 16 x 64
    const int h = blockIdx.x, t = blockIdx.y, b = blockIdx.z;
    const size_t r0 = ((size_t)b*Tt + t) * NN;
    const int tid = threadIdx.x;

    for (int i = tid; i < NN*32; i += 512) {
        int m = i >> 5, d = i & 31;
        const float* row = P + (r0 + m) * 1408 + h*64;
        k1s[m*36+d] = row[256 + d];
        k2s[m*36+d] = row[288 + d];
    }
    for (int i = tid; i < NN*64; i += 512) {
        int m = i >> 6, e = i & 63;
        vs[i] = P[(r0+m)*1408 + 512 + h*64 + e];
    }
    __syncthreads();

    const float lam = g_lam;
    const int w = tid >> 5, l = tid & 31;
    float* qw  = qs + w*64;
    const float gl0 = ln_g[l], gl1 = ln_g[32+l];
    const float bl0 = ln_b[l], bl1 = ln_b[32+l];
    const float sc = 0.17677669529663687f;

    for (int nb = 2*w; nb < 272; nb += 32) {
        #pragma unroll
        for (int qi = 0; qi < 2; qi++) {
            int n = nb + qi;
            int nclamp = n < NN ? n : NN-1;
            const float* qrow = P + (r0+nclamp)*1408 + h*64;
            qw[l] = qrow[l]; qw[32+l] = qrow[32+l];
            __syncwarp();
            float sc1[9], sc2[9];
            #pragma unroll
            for (int mi=0; mi<9; mi++){ sc1[mi]=0.f; sc2[mi]=0.f; }
            #pragma unroll
            for (int dd=0; dd<8; dd++){
                float4 qa = *(const float4*)&qw[dd*4];
                float4 qb = *(const float4*)&qw[32+dd*4];
                #pragma unroll
                for (int mi=0; mi<9; mi++){
                    int m = l + (mi<<5);
                    int mc = m < NN ? m : 0;
                    float4 kA = *(const float4*)&k1s[mc*36 + dd*4];
                    float4 kB = *(const float4*)&k2s[mc*36 + dd*4];
                    sc1[mi] += qa.x*kA.x + qa.y*kA.y + qa.z*kA.z + qa.w*kA.w;
                    sc2[mi] += qb.x*kB.x + qb.y*kB.y + qb.z*kB.z + qb.w*kB.w;
                }
            }
            float mx1 = -1e30f, mx2 = -1e30f;
            #pragma unroll
            for (int mi=0; mi<9; mi++){
                int m = l + (mi<<5);
                if (m < NN){
                    sc1[mi] *= sc; sc2[mi] *= sc;
                    mx1 = fmaxf(mx1, sc1[mi]); mx2 = fmaxf(mx2, sc2[mi]);
                } else { sc1[mi] = -1e30f; sc2[mi] = -1e30f; }
            }
            mx1 = warpMax(mx1); mx2 = warpMax(mx2);
            float sum1 = 0.f, sum2 = 0.f;
            #pragma unroll
            for (int mi=0; mi<9; mi++){
                int m = l + (mi<<5);
                if (m < NN){
                    sc1[mi] = __expf(sc1[mi]-mx1);
                    sc2[mi] = __expf(sc2[mi]-mx2);
                    sum1 += sc1[mi]; sum2 += sc2[mi];
                }
            }
            sum1 = warpSum(sum1); sum2 = warpSum(sum2);
            float inv1 = 1.f/sum1, inv2 = lam/sum2;
            float* pcw = pc + (w*2+qi)*264;
            #pragma unroll
            for (int mi=0; mi<9; mi++){
                int m = l + (mi<<5);
                if (m < NN) pcw[m] = sc1[mi]*inv1 - sc2[mi]*inv2;
            }
            __syncwarp();
        }
        const float* p0 = pc + (w*2+0)*264;
        const float* p1 = pc + (w*2+1)*264;
        float a0a=0.f, a0b=0.f, a1a=0.f, a1b=0.f;
        #pragma unroll 4
        for (int m=0; m<NN; m++){
            float va = vs[m*64+l], vb = vs[m*64+32+l];
            float q0p = p0[m], q1p = p1[m];
            a0a += q0p*va; a0b += q0p*vb;
            a1a += q1p*va; a1b += q1p*vb;
        }
        #pragma unroll
        for (int qi = 0; qi < 2; qi++) {
            int n = nb + qi;
            if (n >= NN) continue;
            float x0 = qi ? a1a : a0a;
            float x1 = qi ? a1b : a0b;
            float mean = warpSum(x0 + x1) * (1.f/64.f);
            float d0 = x0 - mean, d1 = x1 - mean;
            float var = warpSum(d0*d0 + d1*d1) * (1.f/64.f);
            float rstd = rsqrtf(var + 1e-5f);
            float* orow = st + (r0+n)*640 + h*64;
            orow[l]    = (d0*rstd*gl0 + bl0)*0.8f;
            orow[32+l] = (d1*rstd*gl1 + bl1)*0.8f;
        }
        __syncwarp();
    }
}

// ---------------- agg branch attention (pre-mix) ----------------
__global__ __launch_bounds__(256)
void agg_attn(const float* __restrict__ Pa, float* __restrict__ sx, int Ni)
{
    __shared__ float ks[64*65], vsh[64*64], ps[8*64], qs2[8*64];
    const int h = blockIdx.x, t = blockIdx.y, b = blockIdx.z;
    const size_t r0 = ((size_t)b*Tt + t) * Ni;
    const int tid = threadIdx.x;
    for (int i = tid; i < Ni*64; i += 256) {
        int m = i >> 6, d = i & 63;
        const float* row = Pa + (r0+m)*384 + h*64;
        ks[m*65+d]  = row[128 + d];
        vsh[i] = row[256 + d];
    }
    __syncthreads();
    const int w = tid>>5, l = tid&31;
    float* pw = ps  + w*64;
    float* qw = qs2 + w*64;
    for (int n = w; n < Ni; n += 8) {
        const float* qrow = Pa + (r0+n)*384 + h*64;
        qw[l] = qrow[l]; qw[32+l] = qrow[32+l];
        __syncwarp();
        float scv[2];
        #pragma unroll
        for (int mi=0; mi<2; mi++){
            int m = l + (mi<<5);
            float s = -1e30f;
            if (m < Ni){
                const float* kr = ks + m*65;
                float ts = 0.f;
                #pragma unroll
                for (int d=0; d<64; d++) ts += qw[d]*kr[d];
                s = ts * 0.125f;
            }
            scv[mi] = s;
        }
        float mx = warpMax(fmaxf(scv[0], scv[1]));
        float sum = 0.f;
        #pragma unroll
        for (int mi=0; mi<2; mi++){
            int m = l + (mi<<5);
            if (m < Ni){ float e = __expf(scv[mi]-mx); pw[m] = e; sum += e; }
        }
        sum = warpSum(sum);
        __syncwarp();
        float aa = 0.f, ab = 0.f;
        for (int m=0; m<Ni; m++){
            float e = pw[m];
            aa += e*vsh[m*64+l];
            ab += e*vsh[m*64+32+l];
        }
        float inv = 1.f/sum;
        float* o = sx + ((((size_t)b*Tt+t)*2 + h)*Ni + n)*64;
        o[l] = aa*inv; o[32+l] = ab*inv;
        __syncwarp();
    }
}

// ---------------- mix agg branches through M0/M1 ----------------
__global__ __launch_bounds__(128)
void combine_sg(const float* __restrict__ sx0, const float* __restrict__ sx1,
                const float* __restrict__ M0, const float* __restrict__ M1,
                float* __restrict__ sg)
{
    const int n = blockIdx.x, t = blockIdx.y, b = blockIdx.z;
    const int j = threadIdx.x, h = j>>6, d = j&63;
    const size_t bt = (size_t)b*Tt + t;
    float acc = 0.f;
    const float* s0 = sx0 + (bt*2+h)*(32*64) + d;
    #pragma unroll 4
    for (int m=0; m<32; m++) acc += M0[m*NN+n] * s0[m*64];
    const float* s1 = sx1 + (bt*2+h)*(64*64) + d;
    #pragma unroll 4
    for (int m=0; m<64; m++) acc += M1[m*NN+n] * s1[m*64];
    sg[(bt*NN+n)*128 + j] = acc;
}

// ---------------- temporal attention (t_x + tgx fused) ----------------
__global__ __launch_bounds__(128)
void temporal_kernel(const float* __restrict__ P, const float* __restrict__ q_agg,
                     float* __restrict__ st, float* __restrict__ tgx)
{
    extern __shared__ float sm[];
    const int n = blockIdx.x, b = blockIdx.y;
    const int wid = threadIdx.x >> 5, l = threadIdx.x & 31;
    const int w = wid & 1;
    const int half = wid >> 1;
    float* base = sm + w*6240;
    float* kts = base;
    float* vts = base + 1560;
    float* kgs = base + 3096;
    float* vgs = base + 4656;
    float* qp  = sm + 2*6240 + wid*96;
    float* qsh = qp;
    float* psh = qp + 64;
    for (int i = half*768 + l; i < half*768 + 768; i += 32){
        int t = i>>6, d = i&63;
        const float* row = P + (((size_t)b*Tt+t)*NN + n)*1408 + w*64;
        kts[t*65+d] = row[896+d];
        vts[t*64+d] = row[1024+d];
        kgs[t*65+d] = row[1152+d];
        vgs[t*64+d] = row[1280+d];
    }
    __syncthreads();
    for (int tq = half*12; tq < half*12 + 12; tq++){
        const float* qrow = P + (((size_t)b*Tt+tq)*NN + n)*1408 + w*64 + 768;
        qsh[l] = qrow[l]; qsh[32+l] = qrow[32+l];
        __syncwarp();
        float s = -1e30f;
        if (l < Tt){
            const float* kr = kts + l*65;
            float ts = 0.f;
            #pragma unroll
            for (int d=0; d<64; d++) ts += qsh[d]*kr[d];
            s = ts*0.125f;
        }
        float mx = warpMax(s);
        float e = (l < Tt) ? __expf(s-mx) : 0.f;
        float sum = warpSum(e);
        psh[l] = e;
        __syncwarp();
        float aa = 0.f, ab = 0.f;
        #pragma unroll
        for (int ss=0; ss<Tt; ss++){
            float p = psh[ss];
            aa += p*vts[ss*64+l]; ab += p*vts[ss*64+32+l];
        }
        float inv = 1.f/sum;
        float* o = st + (((size_t)b*Tt+tq)*NN + n)*640 + 384 + w*64;
        o[l] = aa*inv; o[32+l] = ab*inv;
        __syncwarp();
    }
    for (int sg_ = half*6; sg_ < half*6 + 6; sg_++){
        const float* qrow = q_agg + ((size_t)n*12 + sg_)*128 + w*64;
        qsh[l] = qrow[l]; qsh[32+l] = qrow[32+l];
        __syncwarp();
        float s = -1e30f;
        if (l < Tt){
            const float* kr = kgs + l*65;
            float ts = 0.f;
            #pragma unroll
            for (int d=0; d<64; d++) ts += qsh[d]*kr[d];
            s = ts*0.125f;
        }
        float mx = warpMax(s);
        float e = (l < Tt) ? __expf(s-mx) : 0.f;
        float sum = warpSum(e);
        psh[l] = e;
        __syncwarp();
        float aa = 0.f, ab = 0.f;
        #pragma unroll
        for (int ss=0; ss<Tt; ss++){
            float p = psh[ss];
            aa += p*vgs[ss*64+l]; ab += p*vgs[ss*64+32+l];
        }
        float inv = 1.f/sum;
        float* o = tgx + (((size_t)b*NN+n)*12 + sg_)*128 + w*64;
        o[l] = aa*inv; o[32+l] = ab*inv;
        __syncwarp();
    }
}

// ---------------- tg: mix tgx through tmp_map -> st cols 512..639 ------------
__global__ __launch_bounds__(128)
void tg_scatter(const float* __restrict__ tmp_map, const float* __restrict__ tgx,
                float* __restrict__ st)
{
    const int n = blockIdx.x, t = blockIdx.y, b = blockIdx.z;
    const int j = threadIdx.x;
    const float* tm = tmp_map + (((size_t)b*NN + n)*Tt + t)*12;
    const float* g  = tgx + ((size_t)b*NN + n)*12*128 + j;
    float acc = 0.f;
    #pragma unroll
    for (int ss=0; ss<12; ss++) acc += tm[ss]*g[ss*128];
    st[(((size_t)b*Tt+t)*NN + n)*640 + 512 + j] = acc;
}

// ---------------- host ----------------
static inline void split_launch(const float* src, __nv_bfloat16* hi, __nv_bfloat16* lo,
                                int n, cudaStream_t s){
    split_bf16<<<(n/4 + 255)/256, 256, 0, s>>>(src, hi, lo, n);
}

extern "C" void kernel_launch(void* const* d_in, const int* in_sizes, int n_in,
                              void* d_out, int out_size)
{
    (void)in_sizes; (void)n_in; (void)out_size;
    const float* x       = (const float*)d_in[0];
    const float* agg_x0  = (const float*)d_in[1];
    const float* agg_x1  = (const float*)d_in[2];
    const float* tmp_map = (const float*)d_in[3];

    float *P, *P0, *P1, *Wcat, *Wcat0, *Wcat1, *sx0, *sx1, *sg, *tgx, *st;
    cudaGetSymbolAddress((void**)&P,     g_P);
    cudaGetSymbolAddress((void**)&P0,    g_P0);
    cudaGetSymbolAddress((void**)&P1,    g_P1);
    cudaGetSymbolAddress((void**)&Wcat,  g_Wcat);
    cudaGetSymbolAddress((void**)&Wcat0, g_Wcat0);
    cudaGetSymbolAddress((void**)&Wcat1, g_Wcat1);
    cudaGetSymbolAddress((void**)&sx0,   g_sx0);
    cudaGetSymbolAddress((void**)&sx1,   g_sx1);
    cudaGetSymbolAddress((void**)&sg,    g_sg);
    cudaGetSymbolAddress((void**)&tgx,   g_tgx);
    cudaGetSymbolAddress((void**)&st,    g_st);

    __nv_bfloat16 *xh,*xl,*a0h,*a0l,*a1h,*a1l,*Wh,*Wl,*W0h,*W0l,*W1h,*W1l;
    __nv_bfloat16 *sgh,*sgl,*Wah,*Wal,*sth,*stl,*Woh,*Wol;
    cudaGetSymbolAddress((void**)&xh,  g_xh);  cudaGetSymbolAddress((void**)&xl,  g_xl);
    cudaGetSymbolAddress((void**)&a0h, g_a0h); cudaGetSymbolAddress((void**)&a0l, g_a0l);
    cudaGetSymbolAddress((void**)&a1h, g_a1h); cudaGetSymbolAddress((void**)&a1l, g_a1l);
    cudaGetSymbolAddress((void**)&Wh,  g_Wh);  cudaGetSymbolAddress((void**)&Wl,  g_Wl);
    cudaGetSymbolAddress((void**)&W0h, g_W0h); cudaGetSymbolAddress((void**)&W0l, g_W0l);
    cudaGetSymbolAddress((void**)&W1h, g_W1h); cudaGetSymbolAddress((void**)&W1l, g_W1l);
    cudaGetSymbolAddress((void**)&sgh, g_sgh); cudaGetSymbolAddress((void**)&sgl, g_sgl);
    cudaGetSymbolAddress((void**)&Wah, g_Wah); cudaGetSymbolAddress((void**)&Wal, g_Wal);
    cudaGetSymbolAddress((void**)&sth, g_sth); cudaGetSymbolAddress((void**)&stl, g_stl);
    cudaGetSymbolAddress((void**)&Woh, g_Woh); cudaGetSymbolAddress((void**)&Wol, g_Wol);

    cudaFuncSetAttribute(gemm_tc,         cudaFuncAttributeMaxDynamicSharedMemorySize, 110592);
    cudaFuncSetAttribute(spatial_kernel,  cudaFuncAttributeMaxDynamicSharedMemorySize, 180960);
    cudaFuncSetAttribute(temporal_kernel, cudaFuncAttributeMaxDynamicSharedMemorySize, 51456);

    cudaStream_t s = 0;
    const size_t W512 = (size_t)512 * sizeof(float);
    cudaMemcpyAsync(Wcat + (size_t)   0*512, d_in[4],  256*W512, cudaMemcpyDeviceToDevice, s);
    cudaMemcpyAsync(Wcat + (size_t) 256*512, d_in[5],  256*W512, cudaMemcpyDeviceToDevice, s);
    cudaMemcpyAsync(Wcat + (size_t) 512*512, d_in[6],  256*W512, cudaMemcpyDeviceToDevice, s);
    cudaMemcpyAsync(Wcat + (size_t) 768*512, d_in[23], 128*W512, cudaMemcpyDeviceToDevice, s);
    cudaMemcpyAsync(Wcat + (size_t) 896*512, d_in[24], 128*W512, cudaMemcpyDeviceToDevice, s);
    cudaMemcpyAsync(Wcat + (size_t)1024*512, d_in[25], 128*W512, cudaMemcpyDeviceToDevice, s);
    cudaMemcpyAsync(Wcat + (size_t)1152*512, d_in[27], 128*W512, cudaMemcpyDeviceToDevice, s);
    cudaMemcpyAsync(Wcat + (size_t)1280*512, d_in[28], 128*W512, cudaMemcpyDeviceToDevice, s);
    cudaMemcpyAsync(Wcat0 + (size_t)  0*512, d_in[13], 128*W512, cudaMemcpyDeviceToDevice, s);
    cudaMemcpyAsync(Wcat0 + (size_t)128*512, d_in[14], 128*W512, cudaMemcpyDeviceToDevice, s);
    cudaMemcpyAsync(Wcat0 + (size_t)256*512, d_in[15], 128*W512, cudaMemcpyDeviceToDevice, s);
    cudaMemcpyAsync(Wcat1 + (size_t)  0*512, d_in[16], 128*W512, cudaMemcpyDeviceToDevice, s);
    cudaMemcpyAsync(Wcat1 + (size_t)128*512, d_in[17], 128*W512, cudaMemcpyDeviceToDevice, s);
    cudaMemcpyAsync(Wcat1 + (size_t)256*512, d_in[18], 128*W512, cudaMemcpyDeviceToDevice, s);

    lam_kernel<<<1,32,0,s>>>((const float*)d_in[7], (const float*)d_in[8],
                             (const float*)d_in[9], (const float*)d_in[10]);

    // splits for projection inputs/weights
    split_launch(x,       xh,  xl,  50496*512, s);
    split_launch(agg_x0,  a0h, a0l, 6144*512, s);
    split_launch(agg_x1,  a1h, a1l, 12288*512, s);
    split_launch(Wcat,    Wh,  Wl,  1408*512, s);
    split_launch(Wcat0,   W0h, W0l, 384*512, s);
    split_launch(Wcat1,   W1h, W1l, 384*512, s);
    split_launch((const float*)d_in[21], Wah, Wal, 128*128, s);
    split_launch((const float*)d_in[29], Woh, Wol, 512*640, s);

    // projections (HMMA bf16, 4-plane single-sweep)
    gemm_tc<<<dim3(11, 789), 256, 110592, s>>>(xh, xl, Wh, Wl, P, nullptr,
                                               512, 1408, 0);
    gemm_tc<<<dim3(3,   96), 256, 110592, s>>>(a0h, a0l, W0h, W0l, P0, nullptr,
                                               512, 384, 0);
    gemm_tc<<<dim3(3,  192), 256, 110592, s>>>(a1h, a1l, W1h, W1l, P1, nullptr,
                                               512, 384, 0);

    // branch 1: spatial diff attention -> st[:,0:256]
    spatial_kernel<<<dim3(4, Tt, Bb), 512, 180960, s>>>(P, st,
        (const float*)d_in[11], (const float*)d_in[12]);

    // branch 2: agg attention + mix + Wagg -> st[:,256:384]
    agg_attn<<<dim3(2, Tt, Bb), 256, 0, s>>>(P0, sx0, 32);
    agg_attn<<<dim3(2, Tt, Bb), 256, 0, s>>>(P1, sx1, 64);
    combine_sg<<<dim3(NN, Tt, Bb), 128, 0, s>>>(sx0, sx1,
        (const float*)d_in[19], (const float*)d_in[20], sg);
    split_launch(sg, sgh, sgl, 50496*128, s);
    gemm_tc<<<dim3(1, 789), 256, 110592, s>>>(sgh, sgl, Wah, Wal, st,
        (const float*)d_in[22], 128, 640, 256);

    // branches 3+4: temporal attention -> st[:,384:512]; tg -> st[:,512:640]
    temporal_kernel<<<dim3(NN, Bb), 128, 51456, s>>>(P, (const float*)d_in[26], st, tgx);
    tg_scatter<<<dim3(NN, Tt, Bb), 128, 0, s>>>(tmp_map, tgx, st);

    // output projection
    split_launch(st, sth, stl, 50496*640, s);
    gemm_tc<<<dim3(4, 789), 256, 110592, s>>>(sth, stl, Woh, Wol, (float*)d_out,
        (const float*)d_in[30], 640, 512, 0);
}

// round 14
// speedup vs baseline: 1.2919x; 1.0565x over previous
#include <cuda_runtime.h>
#include <cuda_bf16.h>
#include <math.h>
#include <stdint.h>

#define Bb 8
#define Tt 24
#define NN 263
#define Dd 512

// ---------------- scratch (static device globals; no allocation) ----------------
__device__ float g_P[71098368];      // 50496 x 1408  x-projections
__device__ float g_P0[2359296];      // 6144 x 384    agg0 projections
__device__ float g_P1[4718592];      // 12288 x 384   agg1 projections
__device__ float g_Wcat[720896];     // 1408 x 512
__device__ float g_Wcat0[196608];    // 384 x 512
__device__ float g_Wcat1[196608];    // 384 x 512
__device__ float g_sx0[786432];      // B*T*2*32*64
__device__ float g_sx1[1572864];     // B*T*2*64*64
__device__ float g_sg[6463488];      // 50496 x 128 (fp32)
__device__ float g_tgx[3231744];     // 8*263*12*128
__device__ float g_st[32317440];     // 50496 x 640 (fp32)
__device__ float g_lam;

// bf16 hi/lo planes
__device__ __nv_bfloat16 g_xh[25853952],  g_xl[25853952];    // 50496 x 512
__device__ __nv_bfloat16 g_a0h[3145728],  g_a0l[3145728];    // 6144 x 512
__device__ __nv_bfloat16 g_a1h[6291456],  g_a1l[6291456];    // 12288 x 512
__device__ __nv_bfloat16 g_Wh[720896],    g_Wl[720896];      // 1408 x 512
__device__ __nv_bfloat16 g_W0h[196608],   g_W0l[196608];     // 384 x 512
__device__ __nv_bfloat16 g_W1h[196608],   g_W1l[196608];     // 384 x 512
__device__ __nv_bfloat16 g_sgh[6463488],  g_sgl[6463488];    // 50496 x 128
__device__ __nv_bfloat16 g_Wah[16384],    g_Wal[16384];      // 128 x 128
__device__ __nv_bfloat16 g_sth[32317440], g_stl[32317440];   // 50496 x 640
__device__ __nv_bfloat16 g_Woh[327680],   g_Wol[327680];     // 512 x 640

// ---------------- helpers ----------------
__device__ __forceinline__ float warpMax(float v){
    #pragma unroll
    for (int o=16;o;o>>=1) v = fmaxf(v, __shfl_xor_sync(0xffffffffu, v, o));
    return v;
}
__device__ __forceinline__ float warpSum(float v){
    #pragma unroll
    for (int o=16;o;o>>=1) v += __shfl_xor_sync(0xffffffffu, v, o);
    return v;
}
__device__ __forceinline__ uint32_t smem_u32(const void* p){
    return (uint32_t)__cvta_generic_to_shared(p);
}
__device__ __forceinline__ void cp16(uint32_t dst, const void* src){
    asm volatile("cp.async.cg.shared.global [%0], [%1], 16;" :: "r"(dst), "l"(src));
}

#define MMA_BF16(c, a, b) \
    asm volatile("mma.sync.aligned.m16n8k16.row.col.f32.bf16.bf16.f32 " \
        "{%0,%1,%2,%3},{%4,%5,%6,%7},{%8,%9},{%0,%1,%2,%3};" \
        : "+f"((c)[0]),"+f"((c)[1]),"+f"((c)[2]),"+f"((c)[3]) \
        : "r"((a)[0]),"r"((a)[1]),"r"((a)[2]),"r"((a)[3]),"r"((b)[0]),"r"((b)[1]))

#define LDSM4(r0,r1,r2,r3,addr) \
    asm volatile("ldmatrix.sync.aligned.m8n8.x4.shared.b16 {%0,%1,%2,%3}, [%4];" \
        : "=r"(r0),"=r"(r1),"=r"(r2),"=r"(r3) : "r"(addr))

// ---------------- split fp32 -> bf16 hi/lo planes ----------------
__global__ __launch_bounds__(256)
void split_bf16(const float* __restrict__ src, __nv_bfloat16* __restrict__ hi,
                __nv_bfloat16* __restrict__ lo, int n)
{
    int i = (blockIdx.x*256 + threadIdx.x)*4;
    if (i >= n) return;
    float4 v = *(const float4*)(src+i);
    __nv_bfloat16 h0=__float2bfloat16(v.x), h1=__float2bfloat16(v.y);
    __nv_bfloat16 h2=__float2bfloat16(v.z), h3=__float2bfloat16(v.w);
    __nv_bfloat16 l0=__float2bfloat16(v.x-__bfloat162float(h0));
    __nv_bfloat16 l1=__float2bfloat16(v.y-__bfloat162float(h1));
    __nv_bfloat16 l2=__float2bfloat16(v.z-__bfloat162float(h2));
    __nv_bfloat16 l3=__float2bfloat16(v.w-__bfloat162float(h3));
    uint32_t wh0 = ((uint32_t)__bfloat16_as_ushort(h1)<<16)|__bfloat16_as_ushort(h0);
    uint32_t wh1 = ((uint32_t)__bfloat16_as_ushort(h3)<<16)|__bfloat16_as_ushort(h2);
    uint32_t wl0 = ((uint32_t)__bfloat16_as_ushort(l1)<<16)|__bfloat16_as_ushort(l0);
    uint32_t wl1 = ((uint32_t)__bfloat16_as_ushort(l3)<<16)|__bfloat16_as_ushort(l2);
    *(uint2*)(hi+i) = make_uint2(wh0, wh1);
    *(uint2*)(lo+i) = make_uint2(wl0, wl1);
}

// ---------------- lam scalar ----------------
__global__ void lam_kernel(const float* __restrict__ lq1, const float* __restrict__ lk1,
                           const float* __restrict__ lq2, const float* __restrict__ lk2)
{
    int l = threadIdx.x;
    float a = lq1[l]*lk1[l];
    float b = lq2[l]*lk2[l];
    a = warpSum(a); b = warpSum(b);
    if (l == 0) g_lam = expf(a) - expf(b) + 0.2f;   // LAMBDA_INIT = 0.2
}

// ---------------- bf16 HMMA NT GEMM, 4-plane tiles, single K sweep ----------------
// C[m, coff+n] = Ah*Bh + Al*Bh + Ah*Bl (+bias[n]); fp32 out.
// BM=64, BN=128, BK=64. Per K-tile: load Ah/Al/Bh/Bl planes once, do all 3 MMA sets.
__global__ __launch_bounds__(256, 2)
void gemm_tc(const __nv_bfloat16* __restrict__ Ah, const __nv_bfloat16* __restrict__ Al,
             const __nv_bfloat16* __restrict__ Bh, const __nv_bfloat16* __restrict__ Bl,
             float* __restrict__ C, const float* __restrict__ bias,
             int K, int ldc, int coff)
{
    extern __shared__ __align__(16) uint8_t smem[];
    const int AH_OFF = 0, AL_OFF = 64*144, BH_OFF = 128*144, BL_OFF = 256*144;
    const int STG = 384*144;
    const int tid = threadIdx.x;
    const int bm = blockIdx.y*64, bn = blockIdx.x*128;
    const int warp = tid>>5, lane = tid&31;
    const int wm = warp & 1, wn = warp >> 1;
    const int g = lane>>2, tg = lane&3;

    const int nkt = K >> 6;

    float acc[2][4][4];
    #pragma unroll
    for (int i=0;i<2;i++)
        #pragma unroll
        for (int j=0;j<4;j++)
            #pragma unroll
            for (int q=0;q<4;q++) acc[i][j][q] = 0.f;

    auto issue_tile = [&](int kt, int buf){
        const int k0 = kt << 6;
        uint8_t* stg = smem + buf*STG;
        #pragma unroll
        for (int i = 0; i < 12; i++){
            int idx = tid + i*256;          // 0..3071
            int row = idx >> 3, ch = idx & 7;
            const __nv_bfloat16* src;
            if      (row < 64)  src = Ah + (size_t)(bm + row      )*K + k0 + ch*8;
            else if (row < 128) src = Al + (size_t)(bm + row - 64 )*K + k0 + ch*8;
            else if (row < 256) src = Bh + (size_t)(bn + row - 128)*K + k0 + ch*8;
            else                src = Bl + (size_t)(bn + row - 256)*K + k0 + ch*8;
            cp16(smem_u32(stg + row*144 + ch*16), src);
        }
        asm volatile("cp.async.commit_group;");
    };

    issue_tile(0, 0);
    if (nkt > 1) issue_tile(1, 1);

    const int arow = wm*32 + (lane & 15);
    const int ach  = lane >> 4;
    const int brow = wn*32 + (lane & 7) + ((lane >> 4) << 3);
    const int bch  = (lane >> 3) & 1;

    for (int t = 0; t < nkt; t++){
        const int buf = t & 1;
        if (t + 1 < nkt) { asm volatile("cp.async.wait_group 1;"); }
        else             { asm volatile("cp.async.wait_group 0;"); }
        __syncthreads();
        const uint8_t* stg = smem + buf*STG;
        #pragma unroll
        for (int kk = 0; kk < 4; kk++){
            uint32_t afh[2][4], afl[2][4];
            #pragma unroll
            for (int mi=0; mi<2; mi++){
                int ro = (arow + mi*16)*144 + (2*kk + ach)*16;
                LDSM4(afh[mi][0], afh[mi][1], afh[mi][2], afh[mi][3],
                      smem_u32(stg + AH_OFF + ro));
                LDSM4(afl[mi][0], afl[mi][1], afl[mi][2], afl[mi][3],
                      smem_u32(stg + AL_OFF + ro));
            }
            uint32_t bfh[4][2], bfl[4][2];
            #pragma unroll
            for (int ni2=0; ni2<2; ni2++){
                int ro = (brow + ni2*16)*144 + (2*kk + bch)*16;
                uint32_t r0,r1,r2,r3;
                LDSM4(r0,r1,r2,r3, smem_u32(stg + BH_OFF + ro));
                bfh[2*ni2][0]=r0;   bfh[2*ni2][1]=r1;
                bfh[2*ni2+1][0]=r2; bfh[2*ni2+1][1]=r3;
                LDSM4(r0,r1,r2,r3, smem_u32(stg + BL_OFF + ro));
                bfl[2*ni2][0]=r0;   bfl[2*ni2][1]=r1;
                bfl[2*ni2+1][0]=r2; bfl[2*ni2+1][1]=r3;
            }
            #pragma unroll
            for (int mi=0; mi<2; mi++)
                #pragma unroll
                for (int ni=0; ni<4; ni++){
                    MMA_BF16(acc[mi][ni], afh[mi], bfh[ni]);
                    MMA_BF16(acc[mi][ni], afl[mi], bfh[ni]);
                    MMA_BF16(acc[mi][ni], afh[mi], bfl[ni]);
                }
        }
        __syncthreads();
        if (t + 2 < nkt) issue_tile(t+2, buf);
    }

    #pragma unroll
    for (int mi=0; mi<2; mi++){
        #pragma unroll
        for (int ni=0; ni<4; ni++){
            int gr = bm + wm*32 + mi*16 + g;
            int gc = bn + wn*32 + ni*8 + 2*tg;
            float b0 = bias ? bias[gc]   : 0.f;
            float b1 = bias ? bias[gc+1] : 0.f;
            float* Cp = C + (size_t)gr*ldc + coff + gc;
            Cp[0] = acc[mi][ni][0] + b0;
            Cp[1] = acc[mi][ni][1] + b1;
            Cp += (size_t)8*ldc;
            Cp[0] = acc[mi][ni][2] + b0;
            Cp[1] = acc[mi][ni][3] + b1;
        }
    }
}

// ---------------- spatial diff-attention (branch 1) -> st cols 0..255 ----------
__global__ __launch_bounds__(512)
void spatial_kernel(const float* __restrict__ P, float* __restrict__ st,
                    const float* __restrict__ ln_g, const float* __restrict__ ln_b)
{
    extern __shared__ float sm[];
    float* k1s = sm;                    // 263 x 36
    float* k2s = k1s + NN*36;           // 263 x 36
    float* vs  = k2s + NN*36;           // 263 x 64
    float* pc  = vs  + NN*64;           // 32 x 264
    float* qs  = pc  + 32*264;          // 16 x 64
    const int h = blockIdx.x, t = blockIdx.y, b = blockIdx.z;
    const size_t r0 = ((size_t)b*Tt + t) * NN;
    const int tid = threadIdx.x;

    for (int i = tid; i < NN*32; i += 512) {
        int m = i >> 5, d = i & 31;
        const float* row = P + (r0 + m) * 1408 + h*64;
        k1s[m*36+d] = row[256 + d];
        k2s[m*36+d] = row[288 + d];
    }
    for (int i = tid; i < NN*64; i += 512) {
        int m = i >> 6, e = i & 63;
        vs[i] = P[(r0+m)*1408 + 512 + h*64 + e];
    }
    __syncthreads();

    const float lam = g_lam;
    const int w = tid >> 5, l = tid & 31;
    float* qw  = qs + w*64;
    const float gl0 = ln_g[l], gl1 = ln_g[32+l];
    const float bl0 = ln_b[l], bl1 = ln_b[32+l];
    const float sc = 0.17677669529663687f;

    for (int nb = 2*w; nb < 272; nb += 32) {
        #pragma unroll
        for (int qi = 0; qi < 2; qi++) {
            int n = nb + qi;
            int nclamp = n < NN ? n : NN-1;
            const float* qrow = P + (r0+nclamp)*1408 + h*64;
            qw[l] = qrow[l]; qw[32+l] = qrow[32+l];
            __syncwarp();
            float sc1[9], sc2[9];
            #pragma unroll
            for (int mi=0; mi<9; mi++){ sc1[mi]=0.f; sc2[mi]=0.f; }
            #pragma unroll
            for (int dd=0; dd<8; dd++){
                float4 qa = *(const float4*)&qw[dd*4];
                float4 qb = *(const float4*)&qw[32+dd*4];
                #pragma unroll
                for (int mi=0; mi<9; mi++){
                    int m = l + (mi<<5);
                    int mc = m < NN ? m : 0;
                    float4 kA = *(const float4*)&k1s[mc*36 + dd*4];
                    float4 kB = *(const float4*)&k2s[mc*36 + dd*4];
                    sc1[mi] += qa.x*kA.x + qa.y*kA.y + qa.z*kA.z + qa.w*kA.w;
                    sc2[mi] += qb.x*kB.x + qb.y*kB.y + qb.z*kB.z + qb.w*kB.w;
                }
            }
            float mx1 = -1e30f, mx2 = -1e30f;
            #pragma unroll
            for (int mi=0; mi<9; mi++){
                int m = l + (mi<<5);
                if (m < NN){
                    sc1[mi] *= sc; sc2[mi] *= sc;
                    mx1 = fmaxf(mx1, sc1[mi]); mx2 = fmaxf(mx2, sc2[mi]);
                } else { sc1[mi] = -1e30f; sc2[mi] = -1e30f; }
            }
            mx1 = warpMax(mx1); mx2 = warpMax(mx2);
            float sum1 = 0.f, sum2 = 0.f;
            #pragma unroll
            for (int mi=0; mi<9; mi++){
                int m = l + (mi<<5);
                if (m < NN){
                    sc1[mi] = __expf(sc1[mi]-mx1);
                    sc2[mi] = __expf(sc2[mi]-mx2);
                    sum1 += sc1[mi]; sum2 += sc2[mi];
                }
            }
            sum1 = warpSum(sum1); sum2 = warpSum(sum2);
            float inv1 = 1.f/sum1, inv2 = lam/sum2;
            float* pcw = pc + (w*2+qi)*264;
            #pragma unroll
            for (int mi=0; mi<9; mi++){
                int m = l + (mi<<5);
                if (m < NN) pcw[m] = sc1[mi]*inv1 - sc2[mi]*inv2;
            }
            __syncwarp();
        }
        const float* p0 = pc + (w*2+0)*264;
        const float* p1 = pc + (w*2+1)*264;
        float a0a=0.f, a0b=0.f, a1a=0.f, a1b=0.f;
        #pragma unroll 4
        for (int m=0; m<NN; m++){
            float va = vs[m*64+l], vb = vs[m*64+32+l];
            float q0p = p0[m], q1p = p1[m];
            a0a += q0p*va; a0b += q0p*vb;
            a1a += q1p*va; a1b += q1p*vb;
        }
        #pragma unroll
        for (int qi = 0; qi < 2; qi++) {
            int n = nb + qi;
            if (n >= NN) continue;
            float x0 = qi ? a1a : a0a;
            float x1 = qi ? a1b : a0b;
            float mean = warpSum(x0 + x1) * (1.f/64.f);
            float d0 = x0 - mean, d1 = x1 - mean;
            float var = warpSum(d0*d0 + d1*d1) * (1.f/64.f);
            float rstd = rsqrtf(var + 1e-5f);
            float* orow = st + (r0+n)*640 + h*64;
            orow[l]    = (d0*rstd*gl0 + bl0)*0.8f;
            orow[32+l] = (d1*rstd*gl1 + bl1)*0.8f;
        }
        __syncwarp();
    }
}

// ---------------- agg branch attention (pre-mix) ----------------
__global__ __launch_bounds__(256)
void agg_attn(const float* __restrict__ Pa, float* __restrict__ sx, int Ni)
{
    __shared__ float ks[64*65], vsh[64*64], ps[8*64], qs2[8*64];
    const int h = blockIdx.x, t = blockIdx.y, b = blockIdx.z;
    const size_t r0 = ((size_t)b*Tt + t) * Ni;
    const int tid = threadIdx.x;
    for (int i = tid; i < Ni*64; i += 256) {
        int m = i >> 6, d = i & 63;
        const float* row = Pa + (r0+m)*384 + h*64;
        ks[m*65+d]  = row[128 + d];
        vsh[i] = row[256 + d];
    }
    __syncthreads();
    const int w = tid>>5, l = tid&31;
    float* pw = ps  + w*64;
    float* qw = qs2 + w*64;
    for (int n = w; n < Ni; n += 8) {
        const float* qrow = Pa + (r0+n)*384 + h*64;
        qw[l] = qrow[l]; qw[32+l] = qrow[32+l];
        __syncwarp();
        float scv[2];
        #pragma unroll
        for (int mi=0; mi<2; mi++){
            int m = l + (mi<<5);
            float s = -1e30f;
            if (m < Ni){
                const float* kr = ks + m*65;
                float ts = 0.f;
                #pragma unroll
                for (int d=0; d<64; d++) ts += qw[d]*kr[d];
                s = ts * 0.125f;
            }
            scv[mi] = s;
        }
        float mx = warpMax(fmaxf(scv[0], scv[1]));
        float sum = 0.f;
        #pragma unroll
        for (int mi=0; mi<2; mi++){
            int m = l + (mi<<5);
            if (m < Ni){ float e = __expf(scv[mi]-mx); pw[m] = e; sum += e; }
        }
        sum = warpSum(sum);
        __syncwarp();
        float aa = 0.f, ab = 0.f;
        for (int m=0; m<Ni; m++){
            float e = pw[m];
            aa += e*vsh[m*64+l];
            ab += e*vsh[m*64+32+l];
        }
        float inv = 1.f/sum;
        float* o = sx + ((((size_t)b*Tt+t)*2 + h)*Ni + n)*64;
        o[l] = aa*inv; o[32+l] = ab*inv;
        __syncwarp();
    }
}

// ---------------- mix agg branches through M0/M1 ----------------
__global__ __launch_bounds__(128)
void combine_sg(const float* __restrict__ sx0, const float* __restrict__ sx1,
                const float* __restrict__ M0, const float* __restrict__ M1,
                float* __restrict__ sg)
{
    const int n = blockIdx.x, t = blockIdx.y, b = blockIdx.z;
    const int j = threadIdx.x, h = j>>6, d = j&63;
    const size_t bt = (size_t)b*Tt + t;
    float acc = 0.f;
    const float* s0 = sx0 + (bt*2+h)*(32*64) + d;
    #pragma unroll 4
    for (int m=0; m<32; m++) acc += M0[m*NN+n] * s0[m*64];
    const float* s1 = sx1 + (bt*2+h)*(64*64) + d;
    #pragma unroll 4
    for (int m=0; m<64; m++) acc += M1[m*NN+n] * s1[m*64];
    sg[(bt*NN+n)*128 + j] = acc;
}

// ---------------- temporal attention (t_x + tgx fused) ----------------
__global__ __launch_bounds__(128)
void temporal_kernel(const float* __restrict__ P, const float* __restrict__ q_agg,
                     float* __restrict__ st, float* __restrict__ tgx)
{
    extern __shared__ float sm[];
    const int n = blockIdx.x, b = blockIdx.y;
    const int wid = threadIdx.x >> 5, l = threadIdx.x & 31;
    const int w = wid & 1;
    const int half = wid >> 1;
    float* base = sm + w*6240;
    float* kts = base;
    float* vts = base + 1560;
    float* kgs = base + 3096;
    float* vgs = base + 4656;
    float* qp  = sm + 2*6240 + wid*96;
    float* qsh = qp;
    float* psh = qp + 64;
    for (int i = half*768 + l; i < half*768 + 768; i += 32){
        int t = i>>6, d = i&63;
        const float* row = P + (((size_t)b*Tt+t)*NN + n)*1408 + w*64;
        kts[t*65+d] = row[896+d];
        vts[t*64+d] = row[1024+d];
        kgs[t*65+d] = row[1152+d];
        vgs[t*64+d] = row[1280+d];
    }
    __syncthreads();
    for (int tq = half*12; tq < half*12 + 12; tq++){
        const float* qrow = P + (((size_t)b*Tt+tq)*NN + n)*1408 + w*64 + 768;
        qsh[l] = qrow[l]; qsh[32+l] = qrow[32+l];
        __syncwarp();
        float s = -1e30f;
        if (l < Tt){
            const float* kr = kts + l*65;
            float ts = 0.f;
            #pragma unroll
            for (int d=0; d<64; d++) ts += qsh[d]*kr[d];
            s = ts*0.125f;
        }
        float mx = warpMax(s);
        float e = (l < Tt) ? __expf(s-mx) : 0.f;
        float sum = warpSum(e);
        psh[l] = e;
        __syncwarp();
        float aa = 0.f, ab = 0.f;
        #pragma unroll
        for (int ss=0; ss<Tt; ss++){
            float p = psh[ss];
            aa += p*vts[ss*64+l]; ab += p*vts[ss*64+32+l];
        }
        float inv = 1.f/sum;
        float* o = st + (((size_t)b*Tt+tq)*NN + n)*640 + 384 + w*64;
        o[l] = aa*inv; o[32+l] = ab*inv;
        __syncwarp();
    }
    for (int sg_ = half*6; sg_ < half*6 + 6; sg_++){
        const float* qrow = q_agg + ((size_t)n*12 + sg_)*128 + w*64;
        qsh[l] = qrow[l]; qsh[32+l] = qrow[32+l];
        __syncwarp();
        float s = -1e30f;
        if (l < Tt){
            const float* kr = kgs + l*65;
            float ts = 0.f;
            #pragma unroll
            for (int d=0; d<64; d++) ts += qsh[d]*kr[d];
            s = ts*0.125f;
        }
        float mx = warpMax(s);
        float e = (l < Tt) ? __expf(s-mx) : 0.f;
        float sum = warpSum(e);
        psh[l] = e;
        __syncwarp();
        float aa = 0.f, ab = 0.f;
        #pragma unroll
        for (int ss=0; ss<Tt; ss++){
            float p = psh[ss];
            aa += p*vgs[ss*64+l]; ab += p*vgs[ss*64+32+l];
        }
        float inv = 1.f/sum;
        float* o = tgx + (((size_t)b*NN+n)*12 + sg_)*128 + w*64;
        o[l] = aa*inv; o[32+l] = ab*inv;
        __syncwarp();
    }
}

// ---------------- tg: mix tgx through tmp_map -> st cols 512..639 ------------
__global__ __launch_bounds__(128)
void tg_scatter(const float* __restrict__ tmp_map, const float* __restrict__ tgx,
                float* __restrict__ st)
{
    const int n = blockIdx.x, t = blockIdx.y, b = blockIdx.z;
    const int j = threadIdx.x;
    const float* tm = tmp_map + (((size_t)b*NN + n)*Tt + t)*12;
    const float* g  = tgx + ((size_t)b*NN + n)*12*128 + j;
    float acc = 0.f;
    #pragma unroll
    for (int ss=0; ss<12; ss++) acc += tm[ss]*g[ss*128];
    st[(((size_t)b*Tt+t)*NN + n)*640 + 512 + j] = acc;
}

// ---------------- host ----------------
static inline void split_launch(const float* src, __nv_bfloat16* hi, __nv_bfloat16* lo,
                                int n, cudaStream_t s){
    split_bf16<<<(n/4 + 255)/256, 256, 0, s>>>(src, hi, lo, n);
}

extern "C" void kernel_launch(void* const* d_in, const int* in_sizes, int n_in,
                              void* d_out, int out_size)
{
    (void)in_sizes; (void)n_in; (void)out_size;
    const float* x       = (const float*)d_in[0];
    const float* agg_x0  = (const float*)d_in[1];
    const float* agg_x1  = (const float*)d_in[2];
    const float* tmp_map = (const float*)d_in[3];

    float *P, *P0, *P1, *Wcat, *Wcat0, *Wcat1, *sx0, *sx1, *sg, *tgx, *st;
    cudaGetSymbolAddress((void**)&P,     g_P);
    cudaGetSymbolAddress((void**)&P0,    g_P0);
    cudaGetSymbolAddress((void**)&P1,    g_P1);
    cudaGetSymbolAddress((void**)&Wcat,  g_Wcat);
    cudaGetSymbolAddress((void**)&Wcat0, g_Wcat0);
    cudaGetSymbolAddress((void**)&Wcat1, g_Wcat1);
    cudaGetSymbolAddress((void**)&sx0,   g_sx0);
    cudaGetSymbolAddress((void**)&sx1,   g_sx1);
    cudaGetSymbolAddress((void**)&sg,    g_sg);
    cudaGetSymbolAddress((void**)&tgx,   g_tgx);
    cudaGetSymbolAddress((void**)&st,    g_st);

    __nv_bfloat16 *xh,*xl,*a0h,*a0l,*a1h,*a1l,*Wh,*Wl,*W0h,*W0l,*W1h,*W1l;
    __nv_bfloat16 *sgh,*sgl,*Wah,*Wal,*sth,*stl,*Woh,*Wol;
    cudaGetSymbolAddress((void**)&xh,  g_xh);  cudaGetSymbolAddress((void**)&xl,  g_xl);
    cudaGetSymbolAddress((void**)&a0h, g_a0h); cudaGetSymbolAddress((void**)&a0l, g_a0l);
    cudaGetSymbolAddress((void**)&a1h, g_a1h); cudaGetSymbolAddress((void**)&a1l, g_a1l);
    cudaGetSymbolAddress((void**)&Wh,  g_Wh);  cudaGetSymbolAddress((void**)&Wl,  g_Wl);
    cudaGetSymbolAddress((void**)&W0h, g_W0h); cudaGetSymbolAddress((void**)&W0l, g_W0l);
    cudaGetSymbolAddress((void**)&W1h, g_W1h); cudaGetSymbolAddress((void**)&W1l, g_W1l);
    cudaGetSymbolAddress((void**)&sgh, g_sgh); cudaGetSymbolAddress((void**)&sgl, g_sgl);
    cudaGetSymbolAddress((void**)&Wah, g_Wah); cudaGetSymbolAddress((void**)&Wal, g_Wal);
    cudaGetSymbolAddress((void**)&sth, g_sth); cudaGetSymbolAddress((void**)&stl, g_stl);
    cudaGetSymbolAddress((void**)&Woh, g_Woh); cudaGetSymbolAddress((void**)&Wol, g_Wol);

    cudaFuncSetAttribute(gemm_tc,         cudaFuncAttributeMaxDynamicSharedMemorySize, 110592);
    cudaFuncSetAttribute(spatial_kernel,  cudaFuncAttributeMaxDynamicSharedMemorySize, 180960);
    cudaFuncSetAttribute(temporal_kernel, cudaFuncAttributeMaxDynamicSharedMemorySize, 51456);

    // streams/events created ONCE (persist for process lifetime; device work per
    // call is identical). Creating them per-call leaks past graph teardown.
    static cudaStream_t s1 = nullptr, s2 = nullptr;
    static cudaEvent_t evSplit = nullptr, evP = nullptr, evT = nullptr, evG = nullptr;
    if (!s1) {
        cudaStreamCreateWithFlags(&s1, cudaStreamNonBlocking);
        cudaStreamCreateWithFlags(&s2, cudaStreamNonBlocking);
        cudaEventCreateWithFlags(&evSplit, cudaEventDisableTiming);
        cudaEventCreateWithFlags(&evP,     cudaEventDisableTiming);
        cudaEventCreateWithFlags(&evT,     cudaEventDisableTiming);
        cudaEventCreateWithFlags(&evG,     cudaEventDisableTiming);
    }
    cudaStream_t s0 = 0;

    const size_t W512 = (size_t)512 * sizeof(float);
    cudaMemcpyAsync(Wcat + (size_t)   0*512, d_in[4],  256*W512, cudaMemcpyDeviceToDevice, s0);
    cudaMemcpyAsync(Wcat + (size_t) 256*512, d_in[5],  256*W512, cudaMemcpyDeviceToDevice, s0);
    cudaMemcpyAsync(Wcat + (size_t) 512*512, d_in[6],  256*W512, cudaMemcpyDeviceToDevice, s0);
    cudaMemcpyAsync(Wcat + (size_t) 768*512, d_in[23], 128*W512, cudaMemcpyDeviceToDevice, s0);
    cudaMemcpyAsync(Wcat + (size_t) 896*512, d_in[24], 128*W512, cudaMemcpyDeviceToDevice, s0);
    cudaMemcpyAsync(Wcat + (size_t)1024*512, d_in[25], 128*W512, cudaMemcpyDeviceToDevice, s0);
    cudaMemcpyAsync(Wcat + (size_t)1152*512, d_in[27], 128*W512, cudaMemcpyDeviceToDevice, s0);
    cudaMemcpyAsync(Wcat + (size_t)1280*512, d_in[28], 128*W512, cudaMemcpyDeviceToDevice, s0);
    cudaMemcpyAsync(Wcat0 + (size_t)  0*512, d_in[13], 128*W512, cudaMemcpyDeviceToDevice, s0);
    cudaMemcpyAsync(Wcat0 + (size_t)128*512, d_in[14], 128*W512, cudaMemcpyDeviceToDevice, s0);
    cudaMemcpyAsync(Wcat0 + (size_t)256*512, d_in[15], 128*W512, cudaMemcpyDeviceToDevice, s0);
    cudaMemcpyAsync(Wcat1 + (size_t)  0*512, d_in[16], 128*W512, cudaMemcpyDeviceToDevice, s0);
    cudaMemcpyAsync(Wcat1 + (size_t)128*512, d_in[17], 128*W512, cudaMemcpyDeviceToDevice, s0);
    cudaMemcpyAsync(Wcat1 + (size_t)256*512, d_in[18], 128*W512, cudaMemcpyDeviceToDevice, s0);

    lam_kernel<<<1,32,0,s0>>>((const float*)d_in[7], (const float*)d_in[8],
                              (const float*)d_in[9], (const float*)d_in[10]);

    // splits for projection inputs/weights (on s0)
    split_launch(x,       xh,  xl,  50496*512, s0);
    split_launch(agg_x0,  a0h, a0l, 6144*512, s0);
    split_launch(agg_x1,  a1h, a1l, 12288*512, s0);
    split_launch(Wcat,    Wh,  Wl,  1408*512, s0);
    split_launch(Wcat0,   W0h, W0l, 384*512, s0);
    split_launch(Wcat1,   W1h, W1l, 384*512, s0);
    split_launch((const float*)d_in[21], Wah, Wal, 128*128, s0);
    split_launch((const float*)d_in[29], Woh, Wol, 512*640, s0);

    // fork: s1 takes the agg branch (independent of P)
    cudaEventRecord(evSplit, s0);
    cudaStreamWaitEvent(s1, evSplit, 0);

    // s1: agg chain -> st[:,256:384]
    gemm_tc<<<dim3(3,   96), 256, 110592, s1>>>(a0h, a0l, W0h, W0l, P0, nullptr,
                                                512, 384, 0);
    gemm_tc<<<dim3(3,  192), 256, 110592, s1>>>(a1h, a1l, W1h, W1l, P1, nullptr,
                                                512, 384, 0);
    agg_attn<<<dim3(2, Tt, Bb), 256, 0, s1>>>(P0, sx0, 32);
    agg_attn<<<dim3(2, Tt, Bb), 256, 0, s1>>>(P1, sx1, 64);
    combine_sg<<<dim3(NN, Tt, Bb), 128, 0, s1>>>(sx0, sx1,
        (const float*)d_in[19], (const float*)d_in[20], sg);
    split_launch(sg, sgh, sgl, 50496*128, s1);
    gemm_tc<<<dim3(1, 789), 256, 110592, s1>>>(sgh, sgl, Wah, Wal, st,
        (const float*)d_in[22], 128, 640, 256);
    cudaEventRecord(evG, s1);

    // s0: big x-projection GEMM
    gemm_tc<<<dim3(11, 789), 256, 110592, s0>>>(xh, xl, Wh, Wl, P, nullptr,
                                                512, 1408, 0);
    cudaEventRecord(evP, s0);

    // s2: temporal branch -> st[:,384:512] + st[:,512:640]
    cudaStreamWaitEvent(s2, evP, 0);
    temporal_kernel<<<dim3(NN, Bb), 128, 51456, s2>>>(P, (const float*)d_in[26], st, tgx);
    tg_scatter<<<dim3(NN, Tt, Bb), 128, 0, s2>>>(tmp_map, tgx, st);
    cudaEventRecord(evT, s2);

    // s0: spatial branch -> st[:,0:256]
    spatial_kernel<<<dim3(4, Tt, Bb), 512, 180960, s0>>>(P, st,
        (const float*)d_in[11], (const float*)d_in[12]);

    // join on s0
    cudaStreamWaitEvent(s0, evG, 0);
    cudaStreamWaitEvent(s0, evT, 0);

    // output projection
    split_launch(st, sth, stl, 50496*640, s0);
    gemm_tc<<<dim3(4, 789), 256, 110592, s0>>>(sth, stl, Woh, Wol, (float*)d_out,
        (const float*)d_in[30], 640, 512, 0);
}